// round 15
// baseline (speedup 1.0000x reference)
#include <cuda_runtime.h>
#include <cuda_fp16.h>
#include <cstdint>

// Problem constants
#define NN   100000
#define EE   400000
#define FIN  128
#define FH   256
#define GG   4096
#define TT   12
#define NLAYER_REST 4
#define SCAN_B 1024
#define NB_SCAN ((NN + SCAN_B - 1) / SCAN_B)   // 98

// ---------------- scratch (device globals) ----------------
__device__ __half g_preH[NN * FH];      // pre-BN activations, fp16 hi
__device__ __half g_aggH[NN * FH];
__device__ __half g_midH[NN * FH];
__device__ __half g_wH[11 * FH * FH];
__device__ __half g_wL[11 * FH * FH];
__device__ float  g_stats[2 * FH];
__device__ float  g_bnscale[FH];
__device__ float  g_bnshift[FH];
__device__ float  g_pool [GG * FH];
__device__ __half g_poolH[GG * FH];
__device__ __half g_poolL[GG * FH];
__device__ float  g_cnt[GG];
__device__ float  g_gmid[GG * FH];
// CSR structures
__device__ int    g_deg[NN];
__device__ int    g_rowptr[NN + 1];
__device__ int    g_col[EE];
__device__ int    g_cursor[NN];
__device__ int    g_bsums[128];

__device__ __forceinline__ uint32_t smem_u32(const void* p) {
    uint32_t a;
    asm("{ .reg .u64 t; cvta.to.shared.u64 t, %1; cvt.u32.u64 %0, t; }" : "=r"(a) : "l"(p));
    return a;
}

// ---------------- CSR build ----------------
__global__ void k_zero_int2(int* __restrict__ a, int* __restrict__ b, int n) {
    int i = blockIdx.x * blockDim.x + threadIdx.x;
    if (i < n) { a[i] = 0; b[i] = 0; }
}
__global__ void k_hist(const int* __restrict__ dst, int* __restrict__ deg) {
    int e = blockIdx.x * blockDim.x + threadIdx.x;
    if (e < EE) atomicAdd(&deg[dst[e]], 1);
}
__global__ void k_scan1(const int* __restrict__ deg, int* __restrict__ rowptr,
                        int* __restrict__ bsums, int n) {
    __shared__ int s[SCAN_B];
    int i = blockIdx.x * SCAN_B + threadIdx.x;
    int v = (i < n) ? deg[i] : 0;
    s[threadIdx.x] = v;
    __syncthreads();
    for (int off = 1; off < SCAN_B; off <<= 1) {
        int t = (threadIdx.x >= off) ? s[threadIdx.x - off] : 0;
        __syncthreads();
        s[threadIdx.x] += t;
        __syncthreads();
    }
    if (i < n) rowptr[i] = s[threadIdx.x] - v;  // exclusive
    if (threadIdx.x == SCAN_B - 1) bsums[blockIdx.x] = s[SCAN_B - 1];
}
__global__ void k_scan2(int* __restrict__ bsums, int nb) {
    __shared__ int s[128];
    int v = (threadIdx.x < nb) ? bsums[threadIdx.x] : 0;
    s[threadIdx.x] = v;
    __syncthreads();
    for (int off = 1; off < 128; off <<= 1) {
        int t = (threadIdx.x >= off) ? s[threadIdx.x - off] : 0;
        __syncthreads();
        s[threadIdx.x] += t;
        __syncthreads();
    }
    if (threadIdx.x < nb) bsums[threadIdx.x] = s[threadIdx.x] - v;  // exclusive
}
__global__ void k_scan3(int* __restrict__ rowptr, const int* __restrict__ bsums, int n) {
    int i = blockIdx.x * blockDim.x + threadIdx.x;
    if (i < n) rowptr[i] += bsums[i / SCAN_B];
    if (i == 0) rowptr[n] = EE;
}
__global__ void k_fill(const int* __restrict__ src, const int* __restrict__ dst,
                       const int* __restrict__ rowptr, int* __restrict__ cursor,
                       int* __restrict__ col) {
    int e = blockIdx.x * blockDim.x + threadIdx.x;
    if (e >= EE) return;
    int d = dst[e];
    int p = atomicAdd(&cursor[d], 1);
    col[rowptr[d] + p] = src[e];
}

// ---------------- BN prep: stats -> scale/shift; zeroes stats after read ---
__global__ void k_bnprep(float* __restrict__ stats, const float* __restrict__ gamma,
                         const float* __restrict__ beta, float* __restrict__ scale,
                         float* __restrict__ shift, int M) {
    int c = threadIdx.x;
    float invM = 1.0f / (float)M;
    float mean = stats[c] * invM;
    float var = stats[FH + c] * invM - mean * mean;
    float inv = rsqrtf(var + 1e-5f);
    float sc = inv * gamma[c];
    scale[c] = sc;
    shift[c] = beta[c] - mean * sc;
    stats[c] = 0.f;
    stats[FH + c] = 0.f;
}

__device__ __forceinline__ void split_store(float4 a, __half* H, __half* L, size_t o2) {
    __half hx = __float2half_rn(a.x), hy = __float2half_rn(a.y);
    __half hz = __float2half_rn(a.z), hw = __float2half_rn(a.w);
    __half lx = __float2half_rn(a.x - __half2float(hx));
    __half ly = __float2half_rn(a.y - __half2float(hy));
    __half lz = __float2half_rn(a.z - __half2float(hz));
    __half lw = __float2half_rn(a.w - __half2float(hw));
    ((__half2*)H)[o2]     = __halves2half2(hx, hy);
    ((__half2*)H)[o2 + 1] = __halves2half2(hz, hw);
    ((__half2*)L)[o2]     = __halves2half2(lx, ly);
    ((__half2*)L)[o2 + 1] = __halves2half2(lz, lw);
}

// ---------------- aggregation (layer 0: raw fp32 input), 8 floats/thread ---
__global__ void k_agg_split(const float* __restrict__ X, const int* __restrict__ rowptr,
                            const int* __restrict__ col, __half* __restrict__ H,
                            int fin, int total) {
    int i = blockIdx.x * blockDim.x + threadIdx.x;
    if (i >= total) return;
    int fc = fin >> 3;
    int node = i / fc;
    int f = (i - node * fc) << 3;
    int beg = __ldg(&rowptr[node]);
    int end = __ldg(&rowptr[node + 1]);
    const float* base = X + (size_t)node * fin + f;
    float4 a0 = *(const float4*)(base);
    float4 a1 = *(const float4*)(base + 4);
    for (int e = beg; e < end; e++) {
        int s = __ldg(&col[e]);
        const float* nb = X + (size_t)s * fin + f;
        float4 v0 = *(const float4*)(nb);
        float4 v1 = *(const float4*)(nb + 4);
        a0.x += v0.x; a0.y += v0.y; a0.z += v0.z; a0.w += v0.w;
        a1.x += v1.x; a1.y += v1.y; a1.z += v1.z; a1.w += v1.w;
    }
    __half2 h0 = __halves2half2(__float2half_rn(a0.x), __float2half_rn(a0.y));
    __half2 h1 = __halves2half2(__float2half_rn(a0.z), __float2half_rn(a0.w));
    __half2 h2 = __halves2half2(__float2half_rn(a1.x), __float2half_rn(a1.y));
    __half2 h3 = __halves2half2(__float2half_rn(a1.z), __float2half_rn(a1.w));
    uint4 o;
    o.x = *(uint32_t*)&h0; o.y = *(uint32_t*)&h1;
    o.z = *(uint32_t*)&h2; o.w = *(uint32_t*)&h3;
    *(uint4*)(H + (size_t)node * fin + f) = o;
}

// ---------------- aggregation with fused BN+ReLU, fp16 in, 8 halves/thread -
__global__ void k_agg_bn_split(const __half* __restrict__ X, const float* __restrict__ scale,
                               const float* __restrict__ shift,
                               const int* __restrict__ rowptr, const int* __restrict__ col,
                               __half* __restrict__ H, int total) {
    int i = blockIdx.x * blockDim.x + threadIdx.x;
    if (i >= total) return;
    int node = i >> 5;                   // FH/8 = 32 chunks per node
    int f = (i & 31) << 3;
    int beg = __ldg(&rowptr[node]);
    int end = __ldg(&rowptr[node + 1]);
    float4 sc0 = *(const float4*)(scale + f);
    float4 sc1 = *(const float4*)(scale + f + 4);
    float4 sh0 = *(const float4*)(shift + f);
    float4 sh1 = *(const float4*)(shift + f + 4);
    float a[8];
    {
        uint4 u = *(const uint4*)(X + (size_t)node * FH + f);
        float2 p0 = __half22float2(*(__half2*)&u.x);
        float2 p1 = __half22float2(*(__half2*)&u.y);
        float2 p2 = __half22float2(*(__half2*)&u.z);
        float2 p3 = __half22float2(*(__half2*)&u.w);
        a[0] = fmaxf(p0.x * sc0.x + sh0.x, 0.f);
        a[1] = fmaxf(p0.y * sc0.y + sh0.y, 0.f);
        a[2] = fmaxf(p1.x * sc0.z + sh0.z, 0.f);
        a[3] = fmaxf(p1.y * sc0.w + sh0.w, 0.f);
        a[4] = fmaxf(p2.x * sc1.x + sh1.x, 0.f);
        a[5] = fmaxf(p2.y * sc1.y + sh1.y, 0.f);
        a[6] = fmaxf(p3.x * sc1.z + sh1.z, 0.f);
        a[7] = fmaxf(p3.y * sc1.w + sh1.w, 0.f);
    }
    for (int e = beg; e < end; e++) {
        int s = __ldg(&col[e]);
        uint4 u = *(const uint4*)(X + (size_t)s * FH + f);
        float2 p0 = __half22float2(*(__half2*)&u.x);
        float2 p1 = __half22float2(*(__half2*)&u.y);
        float2 p2 = __half22float2(*(__half2*)&u.z);
        float2 p3 = __half22float2(*(__half2*)&u.w);
        a[0] += fmaxf(p0.x * sc0.x + sh0.x, 0.f);
        a[1] += fmaxf(p0.y * sc0.y + sh0.y, 0.f);
        a[2] += fmaxf(p1.x * sc0.z + sh0.z, 0.f);
        a[3] += fmaxf(p1.y * sc0.w + sh0.w, 0.f);
        a[4] += fmaxf(p2.x * sc1.x + sh1.x, 0.f);
        a[5] += fmaxf(p2.y * sc1.y + sh1.y, 0.f);
        a[6] += fmaxf(p3.x * sc1.z + sh1.z, 0.f);
        a[7] += fmaxf(p3.y * sc1.w + sh1.w, 0.f);
    }
    __half2 h0 = __halves2half2(__float2half_rn(a[0]), __float2half_rn(a[1]));
    __half2 h1 = __halves2half2(__float2half_rn(a[2]), __float2half_rn(a[3]));
    __half2 h2 = __halves2half2(__float2half_rn(a[4]), __float2half_rn(a[5]));
    __half2 h3 = __halves2half2(__float2half_rn(a[6]), __float2half_rn(a[7]));
    uint4 o;
    o.x = *(uint32_t*)&h0; o.y = *(uint32_t*)&h1;
    o.z = *(uint32_t*)&h2; o.w = *(uint32_t*)&h3;
    *(uint4*)(H + (size_t)node * FH + f) = o;
}

// ---------------- fp16 split-GEMM, full N=256 per CTA, 512 threads ---------
// 16 warps = 4 (M) x 4 (N); warp tile 32x64 — identical fragment math to the
// proven 256-thread version, but A is loaded ONCE per row tile.
// npass=1: Ah*Bh; npass=2: + Ah*Bl; npass=3: + Al*Bh (predictor GEMM)
// mode: 0 = bias, f32 out;  1 = bias+relu, f32 out;
//       2 = bias+relu, fp16-hi out;  3 = bias, fp16-hi out (+stats)
#define NTOT 256
#define LDS_ST 72
#define SMEM_G ((128 + 256) * LDS_ST * 2)   // 55296 B

__global__ void __launch_bounds__(512, 1)
k_gemm_mma(const __half* __restrict__ Ah, const __half* __restrict__ Al,
           const __half* __restrict__ Bh, const __half* __restrict__ Bl,
           const float* __restrict__ bias,
           float* __restrict__ Cout, __half* __restrict__ CoutH,
           float* __restrict__ stats,
           int M, int K, int mode, int npass) {
    extern __shared__ __half sm[];
    __half* As = sm;                    // 128 rows
    __half* Bs = sm + 128 * LDS_ST;     // 256 rows

    const int tid = threadIdx.x;
    const int wid = tid >> 5, lid = tid & 31;
    const int wm = wid & 3, wn = wid >> 2;   // 4 x 4 warp grid
    const int row0 = blockIdx.x * 128;

    float acc[2][8][4];
#pragma unroll
    for (int a = 0; a < 2; a++)
#pragma unroll
        for (int b = 0; b < 8; b++)
#pragma unroll
            for (int c = 0; c < 4; c++) acc[a][b][c] = 0.f;

    const uint32_t asb = smem_u32(As);
    const uint32_t bsb = smem_u32(Bs);

    const int q = lid >> 3, l8 = lid & 7;
    const int a_row = wm * 32 + (q & 1) * 8 + l8;
    const int a_col = (q >> 1) * 8;
    const int b_row = wn * 64 + (q >> 1) * 8 + l8;
    const int b_col = (q & 1) * 8;

    const int nchunk = K >> 6;
    for (int pass = 0; pass < npass; pass++) {
        const __half* Ap = (pass == 2) ? Al : Ah;
        const __half* Bp = (pass == 1) ? Bl : Bh;
        for (int ck = 0; ck < nchunk; ck++) {
            const int k0 = ck << 6;
            __syncthreads();
            // A tile: 128 rows x 64 halves = 1024 uint4 segs / 512 thr = 2 each
#pragma unroll
            for (int i = 0; i < 2; i++) {
                int s = tid + i * 512;
                int r = s >> 3, c = s & 7;
                uint4 v = make_uint4(0, 0, 0, 0);
                if (row0 + r < M)
                    v = *(const uint4*)(Ap + (size_t)(row0 + r) * K + k0 + c * 8);
                *(uint4*)(As + r * LDS_ST + c * 8) = v;
            }
            // B tile: 256 rows x 64 halves = 2048 segs / 512 thr = 4 each
#pragma unroll
            for (int i = 0; i < 4; i++) {
                int s = tid + i * 512;
                int r = s >> 3, c = s & 7;
                uint4 v = *(const uint4*)(Bp + (size_t)r * K + k0 + c * 8);
                *(uint4*)(Bs + r * LDS_ST + c * 8) = v;
            }
            __syncthreads();

#pragma unroll
            for (int ks = 0; ks < 4; ks++) {
                uint32_t af[2][4];
#pragma unroll
                for (int t = 0; t < 2; t++) {
                    uint32_t addr = asb + (uint32_t)(((a_row + t * 16) * LDS_ST + a_col + ks * 16) * 2);
                    asm volatile("ldmatrix.sync.aligned.m8n8.x4.shared.b16 {%0,%1,%2,%3}, [%4];"
                                 : "=r"(af[t][0]), "=r"(af[t][1]), "=r"(af[t][2]), "=r"(af[t][3])
                                 : "r"(addr));
                }
                uint32_t bf[8][2];
#pragma unroll
                for (int g = 0; g < 4; g++) {
                    uint32_t addr = bsb + (uint32_t)(((b_row + g * 16) * LDS_ST + b_col + ks * 16) * 2);
                    uint32_t r0, r1, r2, r3;
                    asm volatile("ldmatrix.sync.aligned.m8n8.x4.shared.b16 {%0,%1,%2,%3}, [%4];"
                                 : "=r"(r0), "=r"(r1), "=r"(r2), "=r"(r3)
                                 : "r"(addr));
                    bf[2 * g][0] = r0; bf[2 * g][1] = r1;
                    bf[2 * g + 1][0] = r2; bf[2 * g + 1][1] = r3;
                }
#pragma unroll
                for (int tm = 0; tm < 2; tm++)
#pragma unroll
                    for (int tn = 0; tn < 8; tn++) {
                        asm volatile(
                            "mma.sync.aligned.m16n8k16.row.col.f32.f16.f16.f32 "
                            "{%0,%1,%2,%3}, {%4,%5,%6,%7}, {%8,%9}, {%0,%1,%2,%3};"
                            : "+f"(acc[tm][tn][0]), "+f"(acc[tm][tn][1]),
                              "+f"(acc[tm][tn][2]), "+f"(acc[tm][tn][3])
                            : "r"(af[tm][0]), "r"(af[tm][1]), "r"(af[tm][2]), "r"(af[tm][3]),
                              "r"(bf[tn][0]), "r"(bf[tn][1]));
                    }
            }
        }
    }

    // epilogue
    const bool do_relu = (mode == 1 || mode == 2);
    const bool f16_out = (mode >= 2);
    const int erow = lid >> 2;
    const int ecol = (lid & 3) * 2;
    float ssum[8][2], ssq[8][2];
    if (stats) {
#pragma unroll
        for (int tn = 0; tn < 8; tn++) {
            ssum[tn][0] = ssum[tn][1] = 0.f;
            ssq[tn][0] = ssq[tn][1] = 0.f;
        }
    }
#pragma unroll
    for (int tm = 0; tm < 2; tm++) {
#pragma unroll
        for (int half_m = 0; half_m < 2; half_m++) {
            int gr = row0 + wm * 32 + tm * 16 + erow + half_m * 8;
            bool ok = (gr < M);
#pragma unroll
            for (int tn = 0; tn < 8; tn++) {
                int gc = wn * 64 + tn * 8 + ecol;
                float v0 = acc[tm][tn][half_m * 2 + 0] + bias[gc];
                float v1 = acc[tm][tn][half_m * 2 + 1] + bias[gc + 1];
                if (do_relu) { v0 = fmaxf(v0, 0.f); v1 = fmaxf(v1, 0.f); }
                if (ok) {
                    if (f16_out) {
                        __half h0 = __float2half_rn(v0), h1 = __float2half_rn(v1);
                        *(__half2*)(CoutH + (size_t)gr * NTOT + gc) = __halves2half2(h0, h1);
                    } else {
                        *(float2*)(Cout + (size_t)gr * NTOT + gc) = make_float2(v0, v1);
                    }
                }
                if (stats) {
                    float a0 = ok ? v0 : 0.f, a1 = ok ? v1 : 0.f;
                    ssum[tn][0] += a0;       ssum[tn][1] += a1;
                    ssq[tn][0]  += a0 * a0;  ssq[tn][1]  += a1 * a1;
                }
            }
        }
    }
    if (stats) {
#pragma unroll
        for (int tn = 0; tn < 8; tn++) {
#pragma unroll
            for (int j = 0; j < 2; j++) {
#pragma unroll
                for (int o = 4; o < 32; o <<= 1) {
                    ssum[tn][j] += __shfl_xor_sync(0xffffffffu, ssum[tn][j], o);
                    ssq[tn][j]  += __shfl_xor_sync(0xffffffffu, ssq[tn][j], o);
                }
            }
        }
        if (erow == 0) {
#pragma unroll
            for (int tn = 0; tn < 8; tn++) {
                int gc = wn * 64 + tn * 8 + ecol;
                atomicAdd(&stats[gc],          ssum[tn][0]);
                atomicAdd(&stats[gc + 1],      ssum[tn][1]);
                atomicAdd(&stats[FH + gc],     ssq[tn][0]);
                atomicAdd(&stats[FH + gc + 1], ssq[tn][1]);
            }
        }
    }
}

// ---------------- elementwise kernels ----------------
__global__ void k_zero(float* p, int n) {
    int i = blockIdx.x * blockDim.x + threadIdx.x;
    if (i < n) p[i] = 0.f;
}
__global__ void k_zero_pool(float* __restrict__ pool, float* __restrict__ cnt) {
    int i = blockIdx.x * blockDim.x + threadIdx.x;
    if (i < GG * FH) pool[i] = 0.f;
    if (i < GG) cnt[i] = 0.f;
}
// ALL weight prep in one launch: 11 slots transposed + hi/lo split
__global__ void k_wprep_all(const float* __restrict__ W1_0, const float* __restrict__ W2_0,
                            const float* __restrict__ W1s, const float* __restrict__ W2s,
                            const float* __restrict__ Wp1,
                            __half* __restrict__ wH, __half* __restrict__ wL) {
    const int S01 = FIN * FH;
    const int S = FH * FH;
    int i = blockIdx.x * blockDim.x + threadIdx.x;
    const float* W;
    int idx, K, slot;
    if (i < S01) { W = W1_0; idx = i; K = FIN; slot = 0; }
    else if (i < S01 + S) { W = W2_0; idx = i - S01; K = FH; slot = 1; }
    else if (i < S01 + S + 4 * S) {
        int r = i - S01 - S;
        int m = r / S; idx = r - m * S; W = W1s + (size_t)m * S; K = FH; slot = 2 + 2 * m;
    }
    else if (i < S01 + S + 8 * S) {
        int r = i - S01 - 5 * S;
        int m = r / S; idx = r - m * S; W = W2s + (size_t)m * S; K = FH; slot = 3 + 2 * m;
    }
    else if (i < S01 + 10 * S) { W = Wp1; idx = i - S01 - 9 * S; K = FH; slot = 10; }
    else return;
    int k = idx / FH, n = idx - k * FH;
    float v = W[idx];
    __half h = __float2half_rn(v);
    size_t off = (size_t)slot * S + (size_t)n * K + k;
    wH[off] = h;
    wL[off] = __float2half_rn(v - __half2float(h));
}

// pool with fused BN+ReLU of the last layer, fp16 input; also counts nodes
__global__ void k_pool_scatter_bn(const __half* __restrict__ X, const float* __restrict__ scale,
                                  const float* __restrict__ shift, const int* __restrict__ batch,
                                  float* __restrict__ pool, float* __restrict__ cnt) {
    int i = blockIdx.x * blockDim.x + threadIdx.x;
    if (i >= NN * (FH / 4)) return;
    int node = i >> 6;
    int f = (i & 63) << 2;
    int b = __ldg(&batch[node]);
    float4 sc = *(const float4*)(scale + f);
    float4 sh = *(const float4*)(shift + f);
    uint2 u = *(const uint2*)(X + (size_t)node * FH + f);
    float2 p0 = __half22float2(*(__half2*)&u.x);
    float2 p1 = __half22float2(*(__half2*)&u.y);
    float4 v = make_float4(p0.x, p0.y, p1.x, p1.y);
    v.x = fmaxf(v.x * sc.x + sh.x, 0.f);
    v.y = fmaxf(v.y * sc.y + sh.y, 0.f);
    v.z = fmaxf(v.z * sc.z + sh.z, 0.f);
    v.w = fmaxf(v.w * sc.w + sh.w, 0.f);
    float* p = pool + (size_t)b * FH + f;
    atomicAdd(p + 0, v.x);
    atomicAdd(p + 1, v.y);
    atomicAdd(p + 2, v.z);
    atomicAdd(p + 3, v.w);
    if ((i & 63) == 0) atomicAdd(&cnt[b], 1.0f);
}
// pool divide + hi/lo split for the predictor GEMM
__global__ void k_pool_div_split(const float* __restrict__ pool, const float* __restrict__ cnt,
                                 __half* __restrict__ H, __half* __restrict__ L) {
    int i = blockIdx.x * blockDim.x + threadIdx.x;
    if (i >= GG * FH / 4) return;
    float c = fmaxf(cnt[i >> 6], 1.0f);
    float inv = 1.0f / c;
    float4 v = ((const float4*)pool)[i];
    v.x *= inv; v.y *= inv; v.z *= inv; v.w *= inv;
    split_store(v, H, L, (size_t)i * 2);
}
__global__ void k_final(const float* __restrict__ gmid, const float* __restrict__ Wp2,
                        const float* __restrict__ bp2, float* __restrict__ out) {
    int i = blockIdx.x * blockDim.x + threadIdx.x;
    if (i >= GG * TT) return;
    int g = i / TT, t = i - g * TT;
    const float* row = gmid + (size_t)g * FH;
    float acc = bp2[t];
#pragma unroll 8
    for (int k = 0; k < FH; k++) acc += row[k] * __ldg(&Wp2[k * TT + t]);
    out[i] = acc;
}

// ---------------- host driver ----------------
extern "C" void kernel_launch(void* const* d_in, const int* in_sizes, int n_in,
                              void* d_out, int out_size) {
    const float* x     = (const float*)d_in[0];
    const int*   ei    = (const int*)d_in[1];
    const int*   batch = (const int*)d_in[2];
    const float* W1_0 = (const float*)d_in[4];
    const float* b1_0 = (const float*)d_in[5];
    const float* W2_0 = (const float*)d_in[6];
    const float* b2_0 = (const float*)d_in[7];
    const float* g_0  = (const float*)d_in[8];
    const float* be_0 = (const float*)d_in[9];
    const float* W1s  = (const float*)d_in[10];
    const float* b1s  = (const float*)d_in[11];
    const float* W2s  = (const float*)d_in[12];
    const float* b2s  = (const float*)d_in[13];
    const float* gs   = (const float*)d_in[14];
    const float* bes  = (const float*)d_in[15];
    const float* Wp1  = (const float*)d_in[16];
    const float* bp1  = (const float*)d_in[17];
    const float* Wp2  = (const float*)d_in[18];
    const float* bp2  = (const float*)d_in[19];
    float* out = (float*)d_out;

    const int* src = ei;
    const int* dst = ei + EE;

    float *stats, *bnscale, *bnshift, *pool, *cnt, *gmid;
    __half *preH, *aggH, *midH, *wH, *wL, *poolH, *poolL;
    int *deg, *rowptr, *col, *cursor, *bsums;
    cudaGetSymbolAddress((void**)&preH,    g_preH);
    cudaGetSymbolAddress((void**)&aggH,    g_aggH);
    cudaGetSymbolAddress((void**)&midH,    g_midH);
    cudaGetSymbolAddress((void**)&wH,      g_wH);
    cudaGetSymbolAddress((void**)&wL,      g_wL);
    cudaGetSymbolAddress((void**)&stats,   g_stats);
    cudaGetSymbolAddress((void**)&bnscale, g_bnscale);
    cudaGetSymbolAddress((void**)&bnshift, g_bnshift);
    cudaGetSymbolAddress((void**)&pool,    g_pool);
    cudaGetSymbolAddress((void**)&poolH,   g_poolH);
    cudaGetSymbolAddress((void**)&poolL,   g_poolL);
    cudaGetSymbolAddress((void**)&cnt,     g_cnt);
    cudaGetSymbolAddress((void**)&gmid,    g_gmid);
    cudaGetSymbolAddress((void**)&deg,     g_deg);
    cudaGetSymbolAddress((void**)&rowptr,  g_rowptr);
    cudaGetSymbolAddress((void**)&col,     g_col);
    cudaGetSymbolAddress((void**)&cursor,  g_cursor);
    cudaGetSymbolAddress((void**)&bsums,   g_bsums);

    cudaFuncSetAttribute(k_gemm_mma, cudaFuncAttributeMaxDynamicSharedMemorySize, SMEM_G);

    const int SLOT = FH * FH;

    // ---- CSR build ----
    k_zero_int2<<<(NN + 255) / 256, 256>>>(deg, cursor, NN);
    k_hist<<<(EE + 255) / 256, 256>>>(dst, deg);
    k_scan1<<<NB_SCAN, SCAN_B>>>(deg, rowptr, bsums, NN);
    k_scan2<<<1, 128>>>(bsums, NB_SCAN);
    k_scan3<<<(NN + 255) / 256, 256>>>(rowptr, bsums, NN);
    k_fill<<<(EE + 255) / 256, 256>>>(src, dst, rowptr, cursor, col);

    // ---- weight prep (single launch) ----
    const int WTOT = FIN * FH + 10 * FH * FH;
    k_wprep_all<<<(WTOT + 255) / 256, 256>>>(W1_0, W2_0, W1s, W2s, Wp1, wH, wL);

    const int GRID_M = (NN + 127) / 128;

    // stats must be zero before layer-0 GEMM2; subsequent zeroing by k_bnprep
    k_zero<<<2, 256>>>(stats, 2 * FH);

    for (int l = 0; l < 1 + NLAYER_REST; l++) {
        int fin = (l == 0) ? FIN : FH;
        const float* b1    = (l == 0) ? b1_0 : b1s + (size_t)(l - 1) * FH;
        const float* b2    = (l == 0) ? b2_0 : b2s + (size_t)(l - 1) * FH;
        const __half* w1H = wH + (size_t)(l == 0 ? 0 : 2 * l) * SLOT;
        const __half* w1L = wL + (size_t)(l == 0 ? 0 : 2 * l) * SLOT;
        const __half* w2H = wH + (size_t)(l == 0 ? 1 : 2 * l + 1) * SLOT;
        const __half* w2L = wL + (size_t)(l == 0 ? 1 : 2 * l + 1) * SLOT;

        if (l == 0) {
            int total = NN * (fin / 8);
            k_agg_split<<<(total + 255) / 256, 256>>>(x, rowptr, col, aggH, fin, total);
        } else {
            const float* gamma = (l == 1) ? g_0  : gs  + (size_t)(l - 2) * FH;
            const float* beta  = (l == 1) ? be_0 : bes + (size_t)(l - 2) * FH;
            k_bnprep<<<1, FH>>>(stats, gamma, beta, bnscale, bnshift, NN);
            int total = NN * (FH / 8);
            k_agg_bn_split<<<(total + 255) / 256, 256>>>(preH, bnscale, bnshift,
                                                         rowptr, col, aggH, total);
        }
        // mid = relu(agg @ W1 + b1): 1-pass fp16
        k_gemm_mma<<<GRID_M, 512, SMEM_G>>>(aggH, aggH, w1H, w1L, b1,
                                            nullptr, midH, nullptr, NN, fin, 2, 1);
        // pre-BN = mid @ W2 + b2 -> preH (fp16 hi) + exact fp32 stats: 1-pass
        k_gemm_mma<<<GRID_M, 512, SMEM_G>>>(midH, midH, w2H, w2L, b2,
                                            nullptr, preH, stats, NN, FH, 3, 1);
    }

    // global mean pool with fused BN(last)+ReLU
    k_bnprep<<<1, FH>>>(stats, gs + (size_t)(NLAYER_REST - 1) * FH,
                        bes + (size_t)(NLAYER_REST - 1) * FH, bnscale, bnshift, NN);
    k_zero_pool<<<(GG * FH + 255) / 256, 256>>>(pool, cnt);
    k_pool_scatter_bn<<<(NN * (FH / 4) + 255) / 256, 256>>>(preH, bnscale, bnshift,
                                                            batch, pool, cnt);
    k_pool_div_split<<<(GG * FH / 4 + 255) / 256, 256>>>(pool, cnt, poolH, poolL);

    // predictor: post-pooling, full 3-pass precision
    k_gemm_mma<<<GG / 128, 512, SMEM_G>>>(poolH, poolL, wH + 10 * SLOT, wL + 10 * SLOT, bp1,
                                          gmid, nullptr, nullptr, GG, FH, 1, 3);
    k_final<<<(GG * TT + 127) / 128, 128>>>(gmid, Wp2, bp2, out);
}

// round 16
// speedup vs baseline: 1.0668x; 1.0668x over previous
#include <cuda_runtime.h>
#include <cuda_fp16.h>
#include <cstdint>

// Problem constants
#define NN   100000
#define EE   400000
#define FIN  128
#define FH   256
#define GG   4096
#define TT   12
#define NLAYER_REST 4
#define SCAN_B 1024
#define NB_SCAN ((NN + SCAN_B - 1) / SCAN_B)   // 98

// ---------------- scratch (device globals) ----------------
__device__ __half g_xH  [NN * FIN];     // fp16 copy of input x
__device__ __half g_preH[NN * FH];      // pre-BN activations, fp16 hi
__device__ __half g_aggH[NN * FH];
__device__ __half g_midH[NN * FH];
__device__ __half g_wH[11 * FH * FH];
__device__ __half g_wL[11 * FH * FH];   // only slot 10 (predictor) is populated
__device__ float  g_stats[2 * FH];
__device__ float  g_bnscale[FH];
__device__ float  g_bnshift[FH];
__device__ float  g_pool [GG * FH];
__device__ __half g_poolH[GG * FH];
__device__ __half g_poolL[GG * FH];
__device__ float  g_cnt[GG];
__device__ float  g_gmid[GG * FH];
// CSR structures
__device__ int    g_deg[NN];
__device__ int    g_rowptr[NN + 1];
__device__ int    g_col[EE];
__device__ int    g_cursor[NN];
__device__ int    g_bsums[128];

__device__ __forceinline__ uint32_t smem_u32(const void* p) {
    uint32_t a;
    asm("{ .reg .u64 t; cvta.to.shared.u64 t, %1; cvt.u32.u64 %0, t; }" : "=r"(a) : "l"(p));
    return a;
}

// ---------------- CSR build ----------------
__global__ void k_zero_int2(int* __restrict__ a, int* __restrict__ b, int n) {
    int i = blockIdx.x * blockDim.x + threadIdx.x;
    if (i < n) { a[i] = 0; b[i] = 0; }
}
__global__ void k_hist(const int* __restrict__ dst, int* __restrict__ deg) {
    int e = blockIdx.x * blockDim.x + threadIdx.x;
    if (e < EE) atomicAdd(&deg[dst[e]], 1);
}
__global__ void k_scan1(const int* __restrict__ deg, int* __restrict__ rowptr,
                        int* __restrict__ bsums, int n) {
    __shared__ int s[SCAN_B];
    int i = blockIdx.x * SCAN_B + threadIdx.x;
    int v = (i < n) ? deg[i] : 0;
    s[threadIdx.x] = v;
    __syncthreads();
    for (int off = 1; off < SCAN_B; off <<= 1) {
        int t = (threadIdx.x >= off) ? s[threadIdx.x - off] : 0;
        __syncthreads();
        s[threadIdx.x] += t;
        __syncthreads();
    }
    if (i < n) rowptr[i] = s[threadIdx.x] - v;  // exclusive
    if (threadIdx.x == SCAN_B - 1) bsums[blockIdx.x] = s[SCAN_B - 1];
}
__global__ void k_scan2(int* __restrict__ bsums, int nb) {
    __shared__ int s[128];
    int v = (threadIdx.x < nb) ? bsums[threadIdx.x] : 0;
    s[threadIdx.x] = v;
    __syncthreads();
    for (int off = 1; off < 128; off <<= 1) {
        int t = (threadIdx.x >= off) ? s[threadIdx.x - off] : 0;
        __syncthreads();
        s[threadIdx.x] += t;
        __syncthreads();
    }
    if (threadIdx.x < nb) bsums[threadIdx.x] = s[threadIdx.x] - v;  // exclusive
}
__global__ void k_scan3(int* __restrict__ rowptr, const int* __restrict__ bsums, int n) {
    int i = blockIdx.x * blockDim.x + threadIdx.x;
    if (i < n) rowptr[i] += bsums[i / SCAN_B];
    if (i == 0) rowptr[n] = EE;
}
__global__ void k_fill(const int* __restrict__ src, const int* __restrict__ dst,
                       const int* __restrict__ rowptr, int* __restrict__ cursor,
                       int* __restrict__ col) {
    int e = blockIdx.x * blockDim.x + threadIdx.x;
    if (e >= EE) return;
    int d = dst[e];
    int p = atomicAdd(&cursor[d], 1);
    col[rowptr[d] + p] = src[e];
}

// ---------------- BN prep: stats -> scale/shift; zeroes stats after read ---
__global__ void k_bnprep(float* __restrict__ stats, const float* __restrict__ gamma,
                         const float* __restrict__ beta, float* __restrict__ scale,
                         float* __restrict__ shift, int M) {
    int c = threadIdx.x;
    float invM = 1.0f / (float)M;
    float mean = stats[c] * invM;
    float var = stats[FH + c] * invM - mean * mean;
    float inv = rsqrtf(var + 1e-5f);
    float sc = inv * gamma[c];
    scale[c] = sc;
    shift[c] = beta[c] - mean * sc;
    stats[c] = 0.f;
    stats[FH + c] = 0.f;
}

__device__ __forceinline__ void split_store(float4 a, __half* H, __half* L, size_t o2) {
    __half hx = __float2half_rn(a.x), hy = __float2half_rn(a.y);
    __half hz = __float2half_rn(a.z), hw = __float2half_rn(a.w);
    __half lx = __float2half_rn(a.x - __half2float(hx));
    __half ly = __float2half_rn(a.y - __half2float(hy));
    __half lz = __float2half_rn(a.z - __half2float(hz));
    __half lw = __float2half_rn(a.w - __half2float(hw));
    ((__half2*)H)[o2]     = __halves2half2(hx, hy);
    ((__half2*)H)[o2 + 1] = __halves2half2(hz, hw);
    ((__half2*)L)[o2]     = __halves2half2(lx, ly);
    ((__half2*)L)[o2 + 1] = __halves2half2(lz, lw);
}

// ---------------- x -> fp16 conversion (once) ----------------
__global__ void k_x2h(const float* __restrict__ X, __half* __restrict__ H, int n8) {
    int i = blockIdx.x * blockDim.x + threadIdx.x;
    if (i >= n8) return;
    const float* p = X + (size_t)i * 8;
    float4 v0 = *(const float4*)(p);
    float4 v1 = *(const float4*)(p + 4);
    __half2 h0 = __halves2half2(__float2half_rn(v0.x), __float2half_rn(v0.y));
    __half2 h1 = __halves2half2(__float2half_rn(v0.z), __float2half_rn(v0.w));
    __half2 h2 = __halves2half2(__float2half_rn(v1.x), __float2half_rn(v1.y));
    __half2 h3 = __halves2half2(__float2half_rn(v1.z), __float2half_rn(v1.w));
    uint4 o;
    o.x = *(uint32_t*)&h0; o.y = *(uint32_t*)&h1;
    o.z = *(uint32_t*)&h2; o.w = *(uint32_t*)&h3;
    *(uint4*)(H + (size_t)i * 8) = o;
}

// ---------------- aggregation (layer 0: fp16 input), 8 halves/thread -------
__global__ void k_agg_split(const __half* __restrict__ X, const int* __restrict__ rowptr,
                            const int* __restrict__ col, __half* __restrict__ H,
                            int fin, int total) {
    int i = blockIdx.x * blockDim.x + threadIdx.x;
    if (i >= total) return;
    int fc = fin >> 3;
    int node = i / fc;
    int f = (i - node * fc) << 3;
    int beg = __ldg(&rowptr[node]);
    int end = __ldg(&rowptr[node + 1]);
    float a[8];
    {
        uint4 u = *(const uint4*)(X + (size_t)node * fin + f);
        float2 p0 = __half22float2(*(__half2*)&u.x);
        float2 p1 = __half22float2(*(__half2*)&u.y);
        float2 p2 = __half22float2(*(__half2*)&u.z);
        float2 p3 = __half22float2(*(__half2*)&u.w);
        a[0] = p0.x; a[1] = p0.y; a[2] = p1.x; a[3] = p1.y;
        a[4] = p2.x; a[5] = p2.y; a[6] = p3.x; a[7] = p3.y;
    }
    for (int e = beg; e < end; e++) {
        int s = __ldg(&col[e]);
        uint4 u = *(const uint4*)(X + (size_t)s * fin + f);
        float2 p0 = __half22float2(*(__half2*)&u.x);
        float2 p1 = __half22float2(*(__half2*)&u.y);
        float2 p2 = __half22float2(*(__half2*)&u.z);
        float2 p3 = __half22float2(*(__half2*)&u.w);
        a[0] += p0.x; a[1] += p0.y; a[2] += p1.x; a[3] += p1.y;
        a[4] += p2.x; a[5] += p2.y; a[6] += p3.x; a[7] += p3.y;
    }
    __half2 h0 = __halves2half2(__float2half_rn(a[0]), __float2half_rn(a[1]));
    __half2 h1 = __halves2half2(__float2half_rn(a[2]), __float2half_rn(a[3]));
    __half2 h2 = __halves2half2(__float2half_rn(a[4]), __float2half_rn(a[5]));
    __half2 h3 = __halves2half2(__float2half_rn(a[6]), __float2half_rn(a[7]));
    uint4 o;
    o.x = *(uint32_t*)&h0; o.y = *(uint32_t*)&h1;
    o.z = *(uint32_t*)&h2; o.w = *(uint32_t*)&h3;
    *(uint4*)(H + (size_t)node * fin + f) = o;
}

// ---------------- aggregation with fused BN+ReLU, fp16 in, 8 halves/thread -
__global__ void k_agg_bn_split(const __half* __restrict__ X, const float* __restrict__ scale,
                               const float* __restrict__ shift,
                               const int* __restrict__ rowptr, const int* __restrict__ col,
                               __half* __restrict__ H, int total) {
    int i = blockIdx.x * blockDim.x + threadIdx.x;
    if (i >= total) return;
    int node = i >> 5;                   // FH/8 = 32 chunks per node
    int f = (i & 31) << 3;
    int beg = __ldg(&rowptr[node]);
    int end = __ldg(&rowptr[node + 1]);
    float4 sc0 = *(const float4*)(scale + f);
    float4 sc1 = *(const float4*)(scale + f + 4);
    float4 sh0 = *(const float4*)(shift + f);
    float4 sh1 = *(const float4*)(shift + f + 4);
    float a[8];
    {
        uint4 u = *(const uint4*)(X + (size_t)node * FH + f);
        float2 p0 = __half22float2(*(__half2*)&u.x);
        float2 p1 = __half22float2(*(__half2*)&u.y);
        float2 p2 = __half22float2(*(__half2*)&u.z);
        float2 p3 = __half22float2(*(__half2*)&u.w);
        a[0] = fmaxf(p0.x * sc0.x + sh0.x, 0.f);
        a[1] = fmaxf(p0.y * sc0.y + sh0.y, 0.f);
        a[2] = fmaxf(p1.x * sc0.z + sh0.z, 0.f);
        a[3] = fmaxf(p1.y * sc0.w + sh0.w, 0.f);
        a[4] = fmaxf(p2.x * sc1.x + sh1.x, 0.f);
        a[5] = fmaxf(p2.y * sc1.y + sh1.y, 0.f);
        a[6] = fmaxf(p3.x * sc1.z + sh1.z, 0.f);
        a[7] = fmaxf(p3.y * sc1.w + sh1.w, 0.f);
    }
    for (int e = beg; e < end; e++) {
        int s = __ldg(&col[e]);
        uint4 u = *(const uint4*)(X + (size_t)s * FH + f);
        float2 p0 = __half22float2(*(__half2*)&u.x);
        float2 p1 = __half22float2(*(__half2*)&u.y);
        float2 p2 = __half22float2(*(__half2*)&u.z);
        float2 p3 = __half22float2(*(__half2*)&u.w);
        a[0] += fmaxf(p0.x * sc0.x + sh0.x, 0.f);
        a[1] += fmaxf(p0.y * sc0.y + sh0.y, 0.f);
        a[2] += fmaxf(p1.x * sc0.z + sh0.z, 0.f);
        a[3] += fmaxf(p1.y * sc0.w + sh0.w, 0.f);
        a[4] += fmaxf(p2.x * sc1.x + sh1.x, 0.f);
        a[5] += fmaxf(p2.y * sc1.y + sh1.y, 0.f);
        a[6] += fmaxf(p3.x * sc1.z + sh1.z, 0.f);
        a[7] += fmaxf(p3.y * sc1.w + sh1.w, 0.f);
    }
    __half2 h0 = __halves2half2(__float2half_rn(a[0]), __float2half_rn(a[1]));
    __half2 h1 = __halves2half2(__float2half_rn(a[2]), __float2half_rn(a[3]));
    __half2 h2 = __halves2half2(__float2half_rn(a[4]), __float2half_rn(a[5]));
    __half2 h3 = __halves2half2(__float2half_rn(a[6]), __float2half_rn(a[7]));
    uint4 o;
    o.x = *(uint32_t*)&h0; o.y = *(uint32_t*)&h1;
    o.z = *(uint32_t*)&h2; o.w = *(uint32_t*)&h3;
    *(uint4*)(H + (size_t)node * FH + f) = o;
}

// ---------------- fp16 split-GEMM on mma.sync (R12-proven structure) -------
// npass=1: Ah*Bh only; npass=2: + Ah*Bl; npass=3: + Al*Bh (predictor GEMM)
// mode: 0 = bias, f32 out;  1 = bias+relu, f32 out;
//       2 = bias+relu, fp16-hi out;  3 = bias, fp16-hi out (+stats)
#define NTOT 256
#define LDS_ST 72

__global__ void __launch_bounds__(256, 2)
k_gemm_mma(const __half* __restrict__ Ah, const __half* __restrict__ Al,
           const __half* __restrict__ Bh, const __half* __restrict__ Bl,
           const float* __restrict__ bias,
           float* __restrict__ Cout, __half* __restrict__ CoutH,
           float* __restrict__ stats,
           int M, int K, int mode, int npass) {
    __shared__ __half As[128 * LDS_ST];
    __shared__ __half Bs[128 * LDS_ST];

    const int tid = threadIdx.x;
    const int wid = tid >> 5, lid = tid & 31;
    const int wm = wid & 3, wn = wid >> 2;
    const int row0 = blockIdx.y * 128;
    const int col0 = blockIdx.x * 128;

    float acc[2][8][4];
#pragma unroll
    for (int a = 0; a < 2; a++)
#pragma unroll
        for (int b = 0; b < 8; b++)
#pragma unroll
            for (int c = 0; c < 4; c++) acc[a][b][c] = 0.f;

    const uint32_t asb = smem_u32(As);
    const uint32_t bsb = smem_u32(Bs);

    const int q = lid >> 3, l8 = lid & 7;
    const int a_row = wm * 32 + (q & 1) * 8 + l8;
    const int a_col = (q >> 1) * 8;
    const int b_row = wn * 64 + (q >> 1) * 8 + l8;
    const int b_col = (q & 1) * 8;

    const int nchunk = K >> 6;
    for (int pass = 0; pass < npass; pass++) {
        const __half* Ap = (pass == 2) ? Al : Ah;
        const __half* Bp = (pass == 1) ? Bl : Bh;
        for (int ck = 0; ck < nchunk; ck++) {
            const int k0 = ck << 6;
            __syncthreads();
#pragma unroll
            for (int i = 0; i < 4; i++) {
                int s = tid + i * 256;
                int r = s >> 3, c = s & 7;
                uint4 v = make_uint4(0, 0, 0, 0);
                if (row0 + r < M)
                    v = *(const uint4*)(Ap + (size_t)(row0 + r) * K + k0 + c * 8);
                *(uint4*)(As + r * LDS_ST + c * 8) = v;
            }
#pragma unroll
            for (int i = 0; i < 4; i++) {
                int s = tid + i * 256;
                int r = s >> 3, c = s & 7;
                uint4 v = *(const uint4*)(Bp + (size_t)(col0 + r) * K + k0 + c * 8);
                *(uint4*)(Bs + r * LDS_ST + c * 8) = v;
            }
            __syncthreads();

#pragma unroll
            for (int ks = 0; ks < 4; ks++) {
                uint32_t af[2][4];
#pragma unroll
                for (int t = 0; t < 2; t++) {
                    uint32_t addr = asb + (uint32_t)(((a_row + t * 16) * LDS_ST + a_col + ks * 16) * 2);
                    asm volatile("ldmatrix.sync.aligned.m8n8.x4.shared.b16 {%0,%1,%2,%3}, [%4];"
                                 : "=r"(af[t][0]), "=r"(af[t][1]), "=r"(af[t][2]), "=r"(af[t][3])
                                 : "r"(addr));
                }
                uint32_t bf[8][2];
#pragma unroll
                for (int g = 0; g < 4; g++) {
                    uint32_t addr = bsb + (uint32_t)(((b_row + g * 16) * LDS_ST + b_col + ks * 16) * 2);
                    uint32_t r0, r1, r2, r3;
                    asm volatile("ldmatrix.sync.aligned.m8n8.x4.shared.b16 {%0,%1,%2,%3}, [%4];"
                                 : "=r"(r0), "=r"(r1), "=r"(r2), "=r"(r3)
                                 : "r"(addr));
                    bf[2 * g][0] = r0; bf[2 * g][1] = r1;
                    bf[2 * g + 1][0] = r2; bf[2 * g + 1][1] = r3;
                }
#pragma unroll
                for (int tm = 0; tm < 2; tm++)
#pragma unroll
                    for (int tn = 0; tn < 8; tn++) {
                        asm volatile(
                            "mma.sync.aligned.m16n8k16.row.col.f32.f16.f16.f32 "
                            "{%0,%1,%2,%3}, {%4,%5,%6,%7}, {%8,%9}, {%0,%1,%2,%3};"
                            : "+f"(acc[tm][tn][0]), "+f"(acc[tm][tn][1]),
                              "+f"(acc[tm][tn][2]), "+f"(acc[tm][tn][3])
                            : "r"(af[tm][0]), "r"(af[tm][1]), "r"(af[tm][2]), "r"(af[tm][3]),
                              "r"(bf[tn][0]), "r"(bf[tn][1]));
                    }
            }
        }
    }

    // epilogue
    const bool do_relu = (mode == 1 || mode == 2);
    const bool f16_out = (mode >= 2);
    const int erow = lid >> 2;
    const int ecol = (lid & 3) * 2;
    float ssum[8][2], ssq[8][2];
    if (stats) {
#pragma unroll
        for (int tn = 0; tn < 8; tn++) {
            ssum[tn][0] = ssum[tn][1] = 0.f;
            ssq[tn][0] = ssq[tn][1] = 0.f;
        }
    }
#pragma unroll
    for (int tm = 0; tm < 2; tm++) {
#pragma unroll
        for (int half_m = 0; half_m < 2; half_m++) {
            int gr = row0 + wm * 32 + tm * 16 + erow + half_m * 8;
            bool ok = (gr < M);
#pragma unroll
            for (int tn = 0; tn < 8; tn++) {
                int gc = col0 + wn * 64 + tn * 8 + ecol;
                float v0 = acc[tm][tn][half_m * 2 + 0] + bias[gc];
                float v1 = acc[tm][tn][half_m * 2 + 1] + bias[gc + 1];
                if (do_relu) { v0 = fmaxf(v0, 0.f); v1 = fmaxf(v1, 0.f); }
                if (ok) {
                    if (f16_out) {
                        __half h0 = __float2half_rn(v0), h1 = __float2half_rn(v1);
                        *(__half2*)(CoutH + (size_t)gr * NTOT + gc) = __halves2half2(h0, h1);
                    } else {
                        *(float2*)(Cout + (size_t)gr * NTOT + gc) = make_float2(v0, v1);
                    }
                }
                if (stats) {
                    float a0 = ok ? v0 : 0.f, a1 = ok ? v1 : 0.f;
                    ssum[tn][0] += a0;       ssum[tn][1] += a1;
                    ssq[tn][0]  += a0 * a0;  ssq[tn][1]  += a1 * a1;
                }
            }
        }
    }
    if (stats) {
#pragma unroll
        for (int tn = 0; tn < 8; tn++) {
#pragma unroll
            for (int j = 0; j < 2; j++) {
#pragma unroll
                for (int o = 4; o < 32; o <<= 1) {
                    ssum[tn][j] += __shfl_xor_sync(0xffffffffu, ssum[tn][j], o);
                    ssq[tn][j]  += __shfl_xor_sync(0xffffffffu, ssq[tn][j], o);
                }
            }
        }
        if (erow == 0) {
#pragma unroll
            for (int tn = 0; tn < 8; tn++) {
                int gc = col0 + wn * 64 + tn * 8 + ecol;
                atomicAdd(&stats[gc],          ssum[tn][0]);
                atomicAdd(&stats[gc + 1],      ssum[tn][1]);
                atomicAdd(&stats[FH + gc],     ssq[tn][0]);
                atomicAdd(&stats[FH + gc + 1], ssq[tn][1]);
            }
        }
    }
}

// ---------------- elementwise kernels ----------------
__global__ void k_zero(float* p, int n) {
    int i = blockIdx.x * blockDim.x + threadIdx.x;
    if (i < n) p[i] = 0.f;
}
__global__ void k_zero_pool(float* __restrict__ pool, float* __restrict__ cnt) {
    int i = blockIdx.x * blockDim.x + threadIdx.x;
    if (i < GG * FH) pool[i] = 0.f;
    if (i < GG) cnt[i] = 0.f;
}
// ALL weight prep in one launch: 11 slots transposed; wL only for slot 10
__global__ void k_wprep_all(const float* __restrict__ W1_0, const float* __restrict__ W2_0,
                            const float* __restrict__ W1s, const float* __restrict__ W2s,
                            const float* __restrict__ Wp1,
                            __half* __restrict__ wH, __half* __restrict__ wL) {
    const int S01 = FIN * FH;
    const int S = FH * FH;
    int i = blockIdx.x * blockDim.x + threadIdx.x;
    const float* W;
    int idx, K, slot;
    if (i < S01) { W = W1_0; idx = i; K = FIN; slot = 0; }
    else if (i < S01 + S) { W = W2_0; idx = i - S01; K = FH; slot = 1; }
    else if (i < S01 + S + 4 * S) {
        int r = i - S01 - S;
        int m = r / S; idx = r - m * S; W = W1s + (size_t)m * S; K = FH; slot = 2 + 2 * m;
    }
    else if (i < S01 + S + 8 * S) {
        int r = i - S01 - 5 * S;
        int m = r / S; idx = r - m * S; W = W2s + (size_t)m * S; K = FH; slot = 3 + 2 * m;
    }
    else if (i < S01 + 10 * S) { W = Wp1; idx = i - S01 - 9 * S; K = FH; slot = 10; }
    else return;
    int k = idx / FH, n = idx - k * FH;
    float v = W[idx];
    __half h = __float2half_rn(v);
    size_t off = (size_t)slot * S + (size_t)n * K + k;
    wH[off] = h;
    if (slot == 10) wL[off] = __float2half_rn(v - __half2float(h));
}

// pool with fused BN+ReLU of the last layer, fp16 input; also counts nodes
__global__ void k_pool_scatter_bn(const __half* __restrict__ X, const float* __restrict__ scale,
                                  const float* __restrict__ shift, const int* __restrict__ batch,
                                  float* __restrict__ pool, float* __restrict__ cnt) {
    int i = blockIdx.x * blockDim.x + threadIdx.x;
    if (i >= NN * (FH / 4)) return;
    int node = i >> 6;
    int f = (i & 63) << 2;
    int b = __ldg(&batch[node]);
    float4 sc = *(const float4*)(scale + f);
    float4 sh = *(const float4*)(shift + f);
    uint2 u = *(const uint2*)(X + (size_t)node * FH + f);
    float2 p0 = __half22float2(*(__half2*)&u.x);
    float2 p1 = __half22float2(*(__half2*)&u.y);
    float4 v = make_float4(p0.x, p0.y, p1.x, p1.y);
    v.x = fmaxf(v.x * sc.x + sh.x, 0.f);
    v.y = fmaxf(v.y * sc.y + sh.y, 0.f);
    v.z = fmaxf(v.z * sc.z + sh.z, 0.f);
    v.w = fmaxf(v.w * sc.w + sh.w, 0.f);
    float* p = pool + (size_t)b * FH + f;
    atomicAdd(p + 0, v.x);
    atomicAdd(p + 1, v.y);
    atomicAdd(p + 2, v.z);
    atomicAdd(p + 3, v.w);
    if ((i & 63) == 0) atomicAdd(&cnt[b], 1.0f);
}
// pool divide + hi/lo split for the predictor GEMM
__global__ void k_pool_div_split(const float* __restrict__ pool, const float* __restrict__ cnt,
                                 __half* __restrict__ H, __half* __restrict__ L) {
    int i = blockIdx.x * blockDim.x + threadIdx.x;
    if (i >= GG * FH / 4) return;
    float c = fmaxf(cnt[i >> 6], 1.0f);
    float inv = 1.0f / c;
    float4 v = ((const float4*)pool)[i];
    v.x *= inv; v.y *= inv; v.z *= inv; v.w *= inv;
    split_store(v, H, L, (size_t)i * 2);
}
__global__ void k_final(const float* __restrict__ gmid, const float* __restrict__ Wp2,
                        const float* __restrict__ bp2, float* __restrict__ out) {
    int i = blockIdx.x * blockDim.x + threadIdx.x;
    if (i >= GG * TT) return;
    int g = i / TT, t = i - g * TT;
    const float* row = gmid + (size_t)g * FH;
    float acc = bp2[t];
#pragma unroll 8
    for (int k = 0; k < FH; k++) acc += row[k] * __ldg(&Wp2[k * TT + t]);
    out[i] = acc;
}

// ---------------- host driver ----------------
extern "C" void kernel_launch(void* const* d_in, const int* in_sizes, int n_in,
                              void* d_out, int out_size) {
    const float* x     = (const float*)d_in[0];
    const int*   ei    = (const int*)d_in[1];
    const int*   batch = (const int*)d_in[2];
    const float* W1_0 = (const float*)d_in[4];
    const float* b1_0 = (const float*)d_in[5];
    const float* W2_0 = (const float*)d_in[6];
    const float* b2_0 = (const float*)d_in[7];
    const float* g_0  = (const float*)d_in[8];
    const float* be_0 = (const float*)d_in[9];
    const float* W1s  = (const float*)d_in[10];
    const float* b1s  = (const float*)d_in[11];
    const float* W2s  = (const float*)d_in[12];
    const float* b2s  = (const float*)d_in[13];
    const float* gs   = (const float*)d_in[14];
    const float* bes  = (const float*)d_in[15];
    const float* Wp1  = (const float*)d_in[16];
    const float* bp1  = (const float*)d_in[17];
    const float* Wp2  = (const float*)d_in[18];
    const float* bp2  = (const float*)d_in[19];
    float* out = (float*)d_out;

    const int* src = ei;
    const int* dst = ei + EE;

    float *stats, *bnscale, *bnshift, *pool, *cnt, *gmid;
    __half *xH, *preH, *aggH, *midH, *wH, *wL, *poolH, *poolL;
    int *deg, *rowptr, *col, *cursor, *bsums;
    cudaGetSymbolAddress((void**)&xH,      g_xH);
    cudaGetSymbolAddress((void**)&preH,    g_preH);
    cudaGetSymbolAddress((void**)&aggH,    g_aggH);
    cudaGetSymbolAddress((void**)&midH,    g_midH);
    cudaGetSymbolAddress((void**)&wH,      g_wH);
    cudaGetSymbolAddress((void**)&wL,      g_wL);
    cudaGetSymbolAddress((void**)&stats,   g_stats);
    cudaGetSymbolAddress((void**)&bnscale, g_bnscale);
    cudaGetSymbolAddress((void**)&bnshift, g_bnshift);
    cudaGetSymbolAddress((void**)&pool,    g_pool);
    cudaGetSymbolAddress((void**)&poolH,   g_poolH);
    cudaGetSymbolAddress((void**)&poolL,   g_poolL);
    cudaGetSymbolAddress((void**)&cnt,     g_cnt);
    cudaGetSymbolAddress((void**)&gmid,    g_gmid);
    cudaGetSymbolAddress((void**)&deg,     g_deg);
    cudaGetSymbolAddress((void**)&rowptr,  g_rowptr);
    cudaGetSymbolAddress((void**)&col,     g_col);
    cudaGetSymbolAddress((void**)&cursor,  g_cursor);
    cudaGetSymbolAddress((void**)&bsums,   g_bsums);

    const int SLOT = FH * FH;

    // ---- CSR build ----
    k_zero_int2<<<(NN + 255) / 256, 256>>>(deg, cursor, NN);
    k_hist<<<(EE + 255) / 256, 256>>>(dst, deg);
    k_scan1<<<NB_SCAN, SCAN_B>>>(deg, rowptr, bsums, NN);
    k_scan2<<<1, 128>>>(bsums, NB_SCAN);
    k_scan3<<<(NN + 255) / 256, 256>>>(rowptr, bsums, NN);
    k_fill<<<(EE + 255) / 256, 256>>>(src, dst, rowptr, cursor, col);

    // ---- weight prep (single launch) + x -> fp16 ----
    const int WTOT = FIN * FH + 10 * FH * FH;
    k_wprep_all<<<(WTOT + 255) / 256, 256>>>(W1_0, W2_0, W1s, W2s, Wp1, wH, wL);
    k_x2h<<<(NN * FIN / 8 + 255) / 256, 256>>>(x, xH, NN * FIN / 8);

    const int GRID_M = (NN + 127) / 128;

    // stats must be zero before layer-0 GEMM2; subsequent zeroing by k_bnprep
    k_zero<<<2, 256>>>(stats, 2 * FH);

    for (int l = 0; l < 1 + NLAYER_REST; l++) {
        int fin = (l == 0) ? FIN : FH;
        const float* b1    = (l == 0) ? b1_0 : b1s + (size_t)(l - 1) * FH;
        const float* b2    = (l == 0) ? b2_0 : b2s + (size_t)(l - 1) * FH;
        const __half* w1H = wH + (size_t)(l == 0 ? 0 : 2 * l) * SLOT;
        const __half* w2H = wH + (size_t)(l == 0 ? 1 : 2 * l + 1) * SLOT;

        if (l == 0) {
            int total = NN * (fin / 8);
            k_agg_split<<<(total + 255) / 256, 256>>>(xH, rowptr, col, aggH, fin, total);
        } else {
            const float* gamma = (l == 1) ? g_0  : gs  + (size_t)(l - 2) * FH;
            const float* beta  = (l == 1) ? be_0 : bes + (size_t)(l - 2) * FH;
            k_bnprep<<<1, FH>>>(stats, gamma, beta, bnscale, bnshift, NN);
            int total = NN * (FH / 8);
            k_agg_bn_split<<<(total + 255) / 256, 256>>>(preH, bnscale, bnshift,
                                                         rowptr, col, aggH, total);
        }
        // mid = relu(agg @ W1 + b1): 1-pass fp16
        k_gemm_mma<<<dim3(2, GRID_M), 256>>>(aggH, aggH, w1H, w1H, b1,
                                             nullptr, midH, nullptr, NN, fin, 2, 1);
        // pre-BN = mid @ W2 + b2 -> preH (fp16 hi) + exact fp32 stats: 1-pass
        k_gemm_mma<<<dim3(2, GRID_M), 256>>>(midH, midH, w2H, w2H, b2,
                                             nullptr, preH, stats, NN, FH, 3, 1);
    }

    // global mean pool with fused BN(last)+ReLU
    k_bnprep<<<1, FH>>>(stats, gs + (size_t)(NLAYER_REST - 1) * FH,
                        bes + (size_t)(NLAYER_REST - 1) * FH, bnscale, bnshift, NN);
    k_zero_pool<<<(GG * FH + 255) / 256, 256>>>(pool, cnt);
    k_pool_scatter_bn<<<(NN * (FH / 4) + 255) / 256, 256>>>(preH, bnscale, bnshift,
                                                            batch, pool, cnt);
    k_pool_div_split<<<(GG * FH / 4 + 255) / 256, 256>>>(pool, cnt, poolH, poolL);

    // predictor: post-pooling, full 3-pass precision
    k_gemm_mma<<<dim3(2, GG / 128), 256>>>(poolH, poolL, wH + 10 * SLOT, wL + 10 * SLOT, bp1,
                                           gmid, nullptr, nullptr, GG, FH, 1, 3);
    k_final<<<(GG * TT + 127) / 128, 128>>>(gmid, Wp2, bp2, out);
}

// round 17
// speedup vs baseline: 1.1003x; 1.0314x over previous
#include <cuda_runtime.h>
#include <cuda_fp16.h>
#include <cstdint>

// Problem constants
#define NN   100000
#define EE   400000
#define FIN  128
#define FH   256
#define GG   4096
#define TT   12
#define NLAYER_REST 4
#define SCAN_B 1024
#define NB_SCAN ((NN + SCAN_B - 1) / SCAN_B)   // 98

// ---------------- scratch (device globals) ----------------
__device__ __half g_xH  [NN * FIN];     // fp16 copy of input x
__device__ __half g_preH[NN * FH];      // pre-BN activations, fp16 hi
__device__ __half g_aggH[NN * FH];
__device__ __half g_midH[NN * FH];
__device__ __half g_wH[11 * FH * FH];
__device__ __half g_wL[11 * FH * FH];   // only slot 10 (predictor) is populated
__device__ float  g_stats[2 * FH];
__device__ float  g_bnscale[FH];
__device__ float  g_bnshift[FH];
__device__ float  g_pool [GG * FH];
__device__ __half g_poolH[GG * FH];
__device__ __half g_poolL[GG * FH];
__device__ float  g_cnt[GG];
__device__ float  g_gmid[GG * FH];
// CSR structures
__device__ int    g_deg[NN];
__device__ int    g_rowptr[NN + 1];
__device__ int    g_col[EE];
__device__ int    g_cursor[NN];
__device__ int    g_bsums[128];

__device__ __forceinline__ uint32_t smem_u32(const void* p) {
    uint32_t a;
    asm("{ .reg .u64 t; cvta.to.shared.u64 t, %1; cvt.u32.u64 %0, t; }" : "=r"(a) : "l"(p));
    return a;
}

// ---------------- CSR build ----------------
__global__ void k_zero_int2(int* __restrict__ a, int* __restrict__ b, int n) {
    int i = blockIdx.x * blockDim.x + threadIdx.x;
    if (i < n) { a[i] = 0; b[i] = 0; }
}
__global__ void k_hist(const int* __restrict__ dst, int* __restrict__ deg) {
    int e = blockIdx.x * blockDim.x + threadIdx.x;
    if (e < EE) atomicAdd(&deg[dst[e]], 1);
}
__global__ void k_scan1(const int* __restrict__ deg, int* __restrict__ rowptr,
                        int* __restrict__ bsums, int n) {
    __shared__ int s[SCAN_B];
    int i = blockIdx.x * SCAN_B + threadIdx.x;
    int v = (i < n) ? deg[i] : 0;
    s[threadIdx.x] = v;
    __syncthreads();
    for (int off = 1; off < SCAN_B; off <<= 1) {
        int t = (threadIdx.x >= off) ? s[threadIdx.x - off] : 0;
        __syncthreads();
        s[threadIdx.x] += t;
        __syncthreads();
    }
    if (i < n) rowptr[i] = s[threadIdx.x] - v;  // exclusive
    if (threadIdx.x == SCAN_B - 1) bsums[blockIdx.x] = s[SCAN_B - 1];
}
__global__ void k_scan2(int* __restrict__ bsums, int nb) {
    __shared__ int s[128];
    int v = (threadIdx.x < nb) ? bsums[threadIdx.x] : 0;
    s[threadIdx.x] = v;
    __syncthreads();
    for (int off = 1; off < 128; off <<= 1) {
        int t = (threadIdx.x >= off) ? s[threadIdx.x - off] : 0;
        __syncthreads();
        s[threadIdx.x] += t;
        __syncthreads();
    }
    if (threadIdx.x < nb) bsums[threadIdx.x] = s[threadIdx.x] - v;  // exclusive
}
__global__ void k_scan3(int* __restrict__ rowptr, const int* __restrict__ bsums, int n) {
    int i = blockIdx.x * blockDim.x + threadIdx.x;
    if (i < n) rowptr[i] += bsums[i / SCAN_B];
    if (i == 0) rowptr[n] = EE;
}
__global__ void k_fill(const int* __restrict__ src, const int* __restrict__ dst,
                       const int* __restrict__ rowptr, int* __restrict__ cursor,
                       int* __restrict__ col) {
    int e = blockIdx.x * blockDim.x + threadIdx.x;
    if (e >= EE) return;
    int d = dst[e];
    int p = atomicAdd(&cursor[d], 1);
    col[rowptr[d] + p] = src[e];
}

// ---------------- BN prep: stats -> scale/shift; zeroes stats after read ---
__global__ void k_bnprep(float* __restrict__ stats, const float* __restrict__ gamma,
                         const float* __restrict__ beta, float* __restrict__ scale,
                         float* __restrict__ shift, int M) {
    int c = threadIdx.x;
    float invM = 1.0f / (float)M;
    float mean = stats[c] * invM;
    float var = stats[FH + c] * invM - mean * mean;
    float inv = rsqrtf(var + 1e-5f);
    float sc = inv * gamma[c];
    scale[c] = sc;
    shift[c] = beta[c] - mean * sc;
    stats[c] = 0.f;
    stats[FH + c] = 0.f;
}

__device__ __forceinline__ void split_store(float4 a, __half* H, __half* L, size_t o2) {
    __half hx = __float2half_rn(a.x), hy = __float2half_rn(a.y);
    __half hz = __float2half_rn(a.z), hw = __float2half_rn(a.w);
    __half lx = __float2half_rn(a.x - __half2float(hx));
    __half ly = __float2half_rn(a.y - __half2float(hy));
    __half lz = __float2half_rn(a.z - __half2float(hz));
    __half lw = __float2half_rn(a.w - __half2float(hw));
    ((__half2*)H)[o2]     = __halves2half2(hx, hy);
    ((__half2*)H)[o2 + 1] = __halves2half2(hz, hw);
    ((__half2*)L)[o2]     = __halves2half2(lx, ly);
    ((__half2*)L)[o2 + 1] = __halves2half2(lz, lw);
}

// ---------------- x -> fp16 conversion (once) ----------------
__global__ void k_x2h(const float* __restrict__ X, __half* __restrict__ H, int n8) {
    int i = blockIdx.x * blockDim.x + threadIdx.x;
    if (i >= n8) return;
    const float* p = X + (size_t)i * 8;
    float4 v0 = *(const float4*)(p);
    float4 v1 = *(const float4*)(p + 4);
    __half2 h0 = __halves2half2(__float2half_rn(v0.x), __float2half_rn(v0.y));
    __half2 h1 = __halves2half2(__float2half_rn(v0.z), __float2half_rn(v0.w));
    __half2 h2 = __halves2half2(__float2half_rn(v1.x), __float2half_rn(v1.y));
    __half2 h3 = __halves2half2(__float2half_rn(v1.z), __float2half_rn(v1.w));
    uint4 o;
    o.x = *(uint32_t*)&h0; o.y = *(uint32_t*)&h1;
    o.z = *(uint32_t*)&h2; o.w = *(uint32_t*)&h3;
    *(uint4*)(H + (size_t)i * 8) = o;
}

// ---------------- aggregation (layer 0: fp16 input), 8 halves/thread -------
__global__ void k_agg_split(const __half* __restrict__ X, const int* __restrict__ rowptr,
                            const int* __restrict__ col, __half* __restrict__ H,
                            int fin, int total) {
    int i = blockIdx.x * blockDim.x + threadIdx.x;
    if (i >= total) return;
    int fc = fin >> 3;
    int node = i / fc;
    int f = (i - node * fc) << 3;
    int beg = __ldg(&rowptr[node]);
    int end = __ldg(&rowptr[node + 1]);
    float a[8];
    {
        uint4 u = *(const uint4*)(X + (size_t)node * fin + f);
        float2 p0 = __half22float2(*(__half2*)&u.x);
        float2 p1 = __half22float2(*(__half2*)&u.y);
        float2 p2 = __half22float2(*(__half2*)&u.z);
        float2 p3 = __half22float2(*(__half2*)&u.w);
        a[0] = p0.x; a[1] = p0.y; a[2] = p1.x; a[3] = p1.y;
        a[4] = p2.x; a[5] = p2.y; a[6] = p3.x; a[7] = p3.y;
    }
    for (int e = beg; e < end; e++) {
        int s = __ldg(&col[e]);
        uint4 u = *(const uint4*)(X + (size_t)s * fin + f);
        float2 p0 = __half22float2(*(__half2*)&u.x);
        float2 p1 = __half22float2(*(__half2*)&u.y);
        float2 p2 = __half22float2(*(__half2*)&u.z);
        float2 p3 = __half22float2(*(__half2*)&u.w);
        a[0] += p0.x; a[1] += p0.y; a[2] += p1.x; a[3] += p1.y;
        a[4] += p2.x; a[5] += p2.y; a[6] += p3.x; a[7] += p3.y;
    }
    __half2 h0 = __halves2half2(__float2half_rn(a[0]), __float2half_rn(a[1]));
    __half2 h1 = __halves2half2(__float2half_rn(a[2]), __float2half_rn(a[3]));
    __half2 h2 = __halves2half2(__float2half_rn(a[4]), __float2half_rn(a[5]));
    __half2 h3 = __halves2half2(__float2half_rn(a[6]), __float2half_rn(a[7]));
    uint4 o;
    o.x = *(uint32_t*)&h0; o.y = *(uint32_t*)&h1;
    o.z = *(uint32_t*)&h2; o.w = *(uint32_t*)&h3;
    *(uint4*)(H + (size_t)node * fin + f) = o;
}

// ---------------- aggregation with fused BN+ReLU, fp16 in, 8 halves/thread -
__global__ void k_agg_bn_split(const __half* __restrict__ X, const float* __restrict__ scale,
                               const float* __restrict__ shift,
                               const int* __restrict__ rowptr, const int* __restrict__ col,
                               __half* __restrict__ H, int total) {
    int i = blockIdx.x * blockDim.x + threadIdx.x;
    if (i >= total) return;
    int node = i >> 5;                   // FH/8 = 32 chunks per node
    int f = (i & 31) << 3;
    int beg = __ldg(&rowptr[node]);
    int end = __ldg(&rowptr[node + 1]);
    float4 sc0 = *(const float4*)(scale + f);
    float4 sc1 = *(const float4*)(scale + f + 4);
    float4 sh0 = *(const float4*)(shift + f);
    float4 sh1 = *(const float4*)(shift + f + 4);
    float a[8];
    {
        uint4 u = *(const uint4*)(X + (size_t)node * FH + f);
        float2 p0 = __half22float2(*(__half2*)&u.x);
        float2 p1 = __half22float2(*(__half2*)&u.y);
        float2 p2 = __half22float2(*(__half2*)&u.z);
        float2 p3 = __half22float2(*(__half2*)&u.w);
        a[0] = fmaxf(p0.x * sc0.x + sh0.x, 0.f);
        a[1] = fmaxf(p0.y * sc0.y + sh0.y, 0.f);
        a[2] = fmaxf(p1.x * sc0.z + sh0.z, 0.f);
        a[3] = fmaxf(p1.y * sc0.w + sh0.w, 0.f);
        a[4] = fmaxf(p2.x * sc1.x + sh1.x, 0.f);
        a[5] = fmaxf(p2.y * sc1.y + sh1.y, 0.f);
        a[6] = fmaxf(p3.x * sc1.z + sh1.z, 0.f);
        a[7] = fmaxf(p3.y * sc1.w + sh1.w, 0.f);
    }
    for (int e = beg; e < end; e++) {
        int s = __ldg(&col[e]);
        uint4 u = *(const uint4*)(X + (size_t)s * FH + f);
        float2 p0 = __half22float2(*(__half2*)&u.x);
        float2 p1 = __half22float2(*(__half2*)&u.y);
        float2 p2 = __half22float2(*(__half2*)&u.z);
        float2 p3 = __half22float2(*(__half2*)&u.w);
        a[0] += fmaxf(p0.x * sc0.x + sh0.x, 0.f);
        a[1] += fmaxf(p0.y * sc0.y + sh0.y, 0.f);
        a[2] += fmaxf(p1.x * sc0.z + sh0.z, 0.f);
        a[3] += fmaxf(p1.y * sc0.w + sh0.w, 0.f);
        a[4] += fmaxf(p2.x * sc1.x + sh1.x, 0.f);
        a[5] += fmaxf(p2.y * sc1.y + sh1.y, 0.f);
        a[6] += fmaxf(p3.x * sc1.z + sh1.z, 0.f);
        a[7] += fmaxf(p3.y * sc1.w + sh1.w, 0.f);
    }
    __half2 h0 = __halves2half2(__float2half_rn(a[0]), __float2half_rn(a[1]));
    __half2 h1 = __halves2half2(__float2half_rn(a[2]), __float2half_rn(a[3]));
    __half2 h2 = __halves2half2(__float2half_rn(a[4]), __float2half_rn(a[5]));
    __half2 h3 = __halves2half2(__float2half_rn(a[6]), __float2half_rn(a[7]));
    uint4 o;
    o.x = *(uint32_t*)&h0; o.y = *(uint32_t*)&h1;
    o.z = *(uint32_t*)&h2; o.w = *(uint32_t*)&h3;
    *(uint4*)(H + (size_t)node * FH + f) = o;
}

// ---------------- fp16 split-GEMM on mma.sync (R12 shape + reg prefetch) ---
// Loads for chunk ck are issued into registers BEFORE the barrier that waits
// on the previous chunk's compute, hiding GMEM latency behind it.
// npass=1: Ah*Bh only; npass=2: + Ah*Bl; npass=3: + Al*Bh (predictor GEMM)
// mode: 0 = bias, f32 out;  1 = bias+relu, f32 out;
//       2 = bias+relu, fp16-hi out;  3 = bias, fp16-hi out (+stats)
#define NTOT 256
#define LDS_ST 72

__global__ void __launch_bounds__(256, 2)
k_gemm_mma(const __half* __restrict__ Ah, const __half* __restrict__ Al,
           const __half* __restrict__ Bh, const __half* __restrict__ Bl,
           const float* __restrict__ bias,
           float* __restrict__ Cout, __half* __restrict__ CoutH,
           float* __restrict__ stats,
           int M, int K, int mode, int npass) {
    __shared__ __half As[128 * LDS_ST];
    __shared__ __half Bs[128 * LDS_ST];

    const int tid = threadIdx.x;
    const int wid = tid >> 5, lid = tid & 31;
    const int wm = wid & 3, wn = wid >> 2;
    const int row0 = blockIdx.y * 128;
    const int col0 = blockIdx.x * 128;

    float acc[2][8][4];
#pragma unroll
    for (int a = 0; a < 2; a++)
#pragma unroll
        for (int b = 0; b < 8; b++)
#pragma unroll
            for (int c = 0; c < 4; c++) acc[a][b][c] = 0.f;

    const uint32_t asb = smem_u32(As);
    const uint32_t bsb = smem_u32(Bs);

    // loader lane mapping (fixed per thread)
    const int ldr = tid >> 3;          // 0..31 base row (stride 32)
    const int ldc = tid & 7;           // column segment
    const bool arow_ok[4] = { row0 + ldr +  0 < M, row0 + ldr + 32 < M,
                              row0 + ldr + 64 < M, row0 + ldr + 96 < M };

    const int q = lid >> 3, l8 = lid & 7;
    const int a_row = wm * 32 + (q & 1) * 8 + l8;
    const int a_col = (q >> 1) * 8;
    const int b_row = wn * 64 + (q >> 1) * 8 + l8;
    const int b_col = (q & 1) * 8;

    const int nchunk = K >> 6;
    for (int pass = 0; pass < npass; pass++) {
        const __half* Ap = (pass == 2) ? Al : Ah;
        const __half* Bp = (pass == 1) ? Bl : Bh;
        for (int ck = 0; ck < nchunk; ck++) {
            const int k0 = ck << 6;
            // ---- prefetch this chunk into registers (overlaps prev compute) ----
            uint4 va[4], vb[4];
#pragma unroll
            for (int i = 0; i < 4; i++) {
                int r = ldr + i * 32;
                va[i] = arow_ok[i] ? *(const uint4*)(Ap + (size_t)(row0 + r) * K + k0 + ldc * 8)
                                   : make_uint4(0, 0, 0, 0);
                vb[i] = *(const uint4*)(Bp + (size_t)(col0 + r) * K + k0 + ldc * 8);
            }
            __syncthreads();           // previous chunk's compute done
#pragma unroll
            for (int i = 0; i < 4; i++) {
                int r = ldr + i * 32;
                *(uint4*)(As + r * LDS_ST + ldc * 8) = va[i];
                *(uint4*)(Bs + r * LDS_ST + ldc * 8) = vb[i];
            }
            __syncthreads();

#pragma unroll
            for (int ks = 0; ks < 4; ks++) {
                uint32_t af[2][4];
#pragma unroll
                for (int t = 0; t < 2; t++) {
                    uint32_t addr = asb + (uint32_t)(((a_row + t * 16) * LDS_ST + a_col + ks * 16) * 2);
                    asm volatile("ldmatrix.sync.aligned.m8n8.x4.shared.b16 {%0,%1,%2,%3}, [%4];"
                                 : "=r"(af[t][0]), "=r"(af[t][1]), "=r"(af[t][2]), "=r"(af[t][3])
                                 : "r"(addr));
                }
                uint32_t bf[8][2];
#pragma unroll
                for (int g = 0; g < 4; g++) {
                    uint32_t addr = bsb + (uint32_t)(((b_row + g * 16) * LDS_ST + b_col + ks * 16) * 2);
                    uint32_t r0, r1, r2, r3;
                    asm volatile("ldmatrix.sync.aligned.m8n8.x4.shared.b16 {%0,%1,%2,%3}, [%4];"
                                 : "=r"(r0), "=r"(r1), "=r"(r2), "=r"(r3)
                                 : "r"(addr));
                    bf[2 * g][0] = r0; bf[2 * g][1] = r1;
                    bf[2 * g + 1][0] = r2; bf[2 * g + 1][1] = r3;
                }
#pragma unroll
                for (int tm = 0; tm < 2; tm++)
#pragma unroll
                    for (int tn = 0; tn < 8; tn++) {
                        asm volatile(
                            "mma.sync.aligned.m16n8k16.row.col.f32.f16.f16.f32 "
                            "{%0,%1,%2,%3}, {%4,%5,%6,%7}, {%8,%9}, {%0,%1,%2,%3};"
                            : "+f"(acc[tm][tn][0]), "+f"(acc[tm][tn][1]),
                              "+f"(acc[tm][tn][2]), "+f"(acc[tm][tn][3])
                            : "r"(af[tm][0]), "r"(af[tm][1]), "r"(af[tm][2]), "r"(af[tm][3]),
                              "r"(bf[tn][0]), "r"(bf[tn][1]));
                    }
            }
        }
    }

    // epilogue
    const bool do_relu = (mode == 1 || mode == 2);
    const bool f16_out = (mode >= 2);
    const int erow = lid >> 2;
    const int ecol = (lid & 3) * 2;
    float ssum[8][2], ssq[8][2];
    if (stats) {
#pragma unroll
        for (int tn = 0; tn < 8; tn++) {
            ssum[tn][0] = ssum[tn][1] = 0.f;
            ssq[tn][0] = ssq[tn][1] = 0.f;
        }
    }
#pragma unroll
    for (int tm = 0; tm < 2; tm++) {
#pragma unroll
        for (int half_m = 0; half_m < 2; half_m++) {
            int gr = row0 + wm * 32 + tm * 16 + erow + half_m * 8;
            bool ok = (gr < M);
#pragma unroll
            for (int tn = 0; tn < 8; tn++) {
                int gc = col0 + wn * 64 + tn * 8 + ecol;
                float v0 = acc[tm][tn][half_m * 2 + 0] + bias[gc];
                float v1 = acc[tm][tn][half_m * 2 + 1] + bias[gc + 1];
                if (do_relu) { v0 = fmaxf(v0, 0.f); v1 = fmaxf(v1, 0.f); }
                if (ok) {
                    if (f16_out) {
                        __half h0 = __float2half_rn(v0), h1 = __float2half_rn(v1);
                        *(__half2*)(CoutH + (size_t)gr * NTOT + gc) = __halves2half2(h0, h1);
                    } else {
                        *(float2*)(Cout + (size_t)gr * NTOT + gc) = make_float2(v0, v1);
                    }
                }
                if (stats) {
                    float a0 = ok ? v0 : 0.f, a1 = ok ? v1 : 0.f;
                    ssum[tn][0] += a0;       ssum[tn][1] += a1;
                    ssq[tn][0]  += a0 * a0;  ssq[tn][1]  += a1 * a1;
                }
            }
        }
    }
    if (stats) {
#pragma unroll
        for (int tn = 0; tn < 8; tn++) {
#pragma unroll
            for (int j = 0; j < 2; j++) {
#pragma unroll
                for (int o = 4; o < 32; o <<= 1) {
                    ssum[tn][j] += __shfl_xor_sync(0xffffffffu, ssum[tn][j], o);
                    ssq[tn][j]  += __shfl_xor_sync(0xffffffffu, ssq[tn][j], o);
                }
            }
        }
        if (erow == 0) {
#pragma unroll
            for (int tn = 0; tn < 8; tn++) {
                int gc = col0 + wn * 64 + tn * 8 + ecol;
                atomicAdd(&stats[gc],          ssum[tn][0]);
                atomicAdd(&stats[gc + 1],      ssum[tn][1]);
                atomicAdd(&stats[FH + gc],     ssq[tn][0]);
                atomicAdd(&stats[FH + gc + 1], ssq[tn][1]);
            }
        }
    }
}

// ---------------- elementwise kernels ----------------
__global__ void k_zero(float* p, int n) {
    int i = blockIdx.x * blockDim.x + threadIdx.x;
    if (i < n) p[i] = 0.f;
}
__global__ void k_zero_pool(float* __restrict__ pool, float* __restrict__ cnt) {
    int i = blockIdx.x * blockDim.x + threadIdx.x;
    if (i < GG * FH) pool[i] = 0.f;
    if (i < GG) cnt[i] = 0.f;
}
// ALL weight prep in one launch: 11 slots transposed; wL only for slot 10
__global__ void k_wprep_all(const float* __restrict__ W1_0, const float* __restrict__ W2_0,
                            const float* __restrict__ W1s, const float* __restrict__ W2s,
                            const float* __restrict__ Wp1,
                            __half* __restrict__ wH, __half* __restrict__ wL) {
    const int S01 = FIN * FH;
    const int S = FH * FH;
    int i = blockIdx.x * blockDim.x + threadIdx.x;
    const float* W;
    int idx, K, slot;
    if (i < S01) { W = W1_0; idx = i; K = FIN; slot = 0; }
    else if (i < S01 + S) { W = W2_0; idx = i - S01; K = FH; slot = 1; }
    else if (i < S01 + S + 4 * S) {
        int r = i - S01 - S;
        int m = r / S; idx = r - m * S; W = W1s + (size_t)m * S; K = FH; slot = 2 + 2 * m;
    }
    else if (i < S01 + S + 8 * S) {
        int r = i - S01 - 5 * S;
        int m = r / S; idx = r - m * S; W = W2s + (size_t)m * S; K = FH; slot = 3 + 2 * m;
    }
    else if (i < S01 + 10 * S) { W = Wp1; idx = i - S01 - 9 * S; K = FH; slot = 10; }
    else return;
    int k = idx / FH, n = idx - k * FH;
    float v = W[idx];
    __half h = __float2half_rn(v);
    size_t off = (size_t)slot * S + (size_t)n * K + k;
    wH[off] = h;
    if (slot == 10) wL[off] = __float2half_rn(v - __half2float(h));
}

// pool with fused BN+ReLU of the last layer, fp16 input; also counts nodes
__global__ void k_pool_scatter_bn(const __half* __restrict__ X, const float* __restrict__ scale,
                                  const float* __restrict__ shift, const int* __restrict__ batch,
                                  float* __restrict__ pool, float* __restrict__ cnt) {
    int i = blockIdx.x * blockDim.x + threadIdx.x;
    if (i >= NN * (FH / 4)) return;
    int node = i >> 6;
    int f = (i & 63) << 2;
    int b = __ldg(&batch[node]);
    float4 sc = *(const float4*)(scale + f);
    float4 sh = *(const float4*)(shift + f);
    uint2 u = *(const uint2*)(X + (size_t)node * FH + f);
    float2 p0 = __half22float2(*(__half2*)&u.x);
    float2 p1 = __half22float2(*(__half2*)&u.y);
    float4 v = make_float4(p0.x, p0.y, p1.x, p1.y);
    v.x = fmaxf(v.x * sc.x + sh.x, 0.f);
    v.y = fmaxf(v.y * sc.y + sh.y, 0.f);
    v.z = fmaxf(v.z * sc.z + sh.z, 0.f);
    v.w = fmaxf(v.w * sc.w + sh.w, 0.f);
    float* p = pool + (size_t)b * FH + f;
    atomicAdd(p + 0, v.x);
    atomicAdd(p + 1, v.y);
    atomicAdd(p + 2, v.z);
    atomicAdd(p + 3, v.w);
    if ((i & 63) == 0) atomicAdd(&cnt[b], 1.0f);
}
// pool divide + hi/lo split for the predictor GEMM
__global__ void k_pool_div_split(const float* __restrict__ pool, const float* __restrict__ cnt,
                                 __half* __restrict__ H, __half* __restrict__ L) {
    int i = blockIdx.x * blockDim.x + threadIdx.x;
    if (i >= GG * FH / 4) return;
    float c = fmaxf(cnt[i >> 6], 1.0f);
    float inv = 1.0f / c;
    float4 v = ((const float4*)pool)[i];
    v.x *= inv; v.y *= inv; v.z *= inv; v.w *= inv;
    split_store(v, H, L, (size_t)i * 2);
}
__global__ void k_final(const float* __restrict__ gmid, const float* __restrict__ Wp2,
                        const float* __restrict__ bp2, float* __restrict__ out) {
    int i = blockIdx.x * blockDim.x + threadIdx.x;
    if (i >= GG * TT) return;
    int g = i / TT, t = i - g * TT;
    const float* row = gmid + (size_t)g * FH;
    float acc = bp2[t];
#pragma unroll 8
    for (int k = 0; k < FH; k++) acc += row[k] * __ldg(&Wp2[k * TT + t]);
    out[i] = acc;
}

// ---------------- host driver ----------------
extern "C" void kernel_launch(void* const* d_in, const int* in_sizes, int n_in,
                              void* d_out, int out_size) {
    const float* x     = (const float*)d_in[0];
    const int*   ei    = (const int*)d_in[1];
    const int*   batch = (const int*)d_in[2];
    const float* W1_0 = (const float*)d_in[4];
    const float* b1_0 = (const float*)d_in[5];
    const float* W2_0 = (const float*)d_in[6];
    const float* b2_0 = (const float*)d_in[7];
    const float* g_0  = (const float*)d_in[8];
    const float* be_0 = (const float*)d_in[9];
    const float* W1s  = (const float*)d_in[10];
    const float* b1s  = (const float*)d_in[11];
    const float* W2s  = (const float*)d_in[12];
    const float* b2s  = (const float*)d_in[13];
    const float* gs   = (const float*)d_in[14];
    const float* bes  = (const float*)d_in[15];
    const float* Wp1  = (const float*)d_in[16];
    const float* bp1  = (const float*)d_in[17];
    const float* Wp2  = (const float*)d_in[18];
    const float* bp2  = (const float*)d_in[19];
    float* out = (float*)d_out;

    const int* src = ei;
    const int* dst = ei + EE;

    float *stats, *bnscale, *bnshift, *pool, *cnt, *gmid;
    __half *xH, *preH, *aggH, *midH, *wH, *wL, *poolH, *poolL;
    int *deg, *rowptr, *col, *cursor, *bsums;
    cudaGetSymbolAddress((void**)&xH,      g_xH);
    cudaGetSymbolAddress((void**)&preH,    g_preH);
    cudaGetSymbolAddress((void**)&aggH,    g_aggH);
    cudaGetSymbolAddress((void**)&midH,    g_midH);
    cudaGetSymbolAddress((void**)&wH,      g_wH);
    cudaGetSymbolAddress((void**)&wL,      g_wL);
    cudaGetSymbolAddress((void**)&stats,   g_stats);
    cudaGetSymbolAddress((void**)&bnscale, g_bnscale);
    cudaGetSymbolAddress((void**)&bnshift, g_bnshift);
    cudaGetSymbolAddress((void**)&pool,    g_pool);
    cudaGetSymbolAddress((void**)&poolH,   g_poolH);
    cudaGetSymbolAddress((void**)&poolL,   g_poolL);
    cudaGetSymbolAddress((void**)&cnt,     g_cnt);
    cudaGetSymbolAddress((void**)&gmid,    g_gmid);
    cudaGetSymbolAddress((void**)&deg,     g_deg);
    cudaGetSymbolAddress((void**)&rowptr,  g_rowptr);
    cudaGetSymbolAddress((void**)&col,     g_col);
    cudaGetSymbolAddress((void**)&cursor,  g_cursor);
    cudaGetSymbolAddress((void**)&bsums,   g_bsums);

    const int SLOT = FH * FH;

    // ---- CSR build ----
    k_zero_int2<<<(NN + 255) / 256, 256>>>(deg, cursor, NN);
    k_hist<<<(EE + 255) / 256, 256>>>(dst, deg);
    k_scan1<<<NB_SCAN, SCAN_B>>>(deg, rowptr, bsums, NN);
    k_scan2<<<1, 128>>>(bsums, NB_SCAN);
    k_scan3<<<(NN + 255) / 256, 256>>>(rowptr, bsums, NN);
    k_fill<<<(EE + 255) / 256, 256>>>(src, dst, rowptr, cursor, col);

    // ---- weight prep (single launch) + x -> fp16 ----
    const int WTOT = FIN * FH + 10 * FH * FH;
    k_wprep_all<<<(WTOT + 255) / 256, 256>>>(W1_0, W2_0, W1s, W2s, Wp1, wH, wL);
    k_x2h<<<(NN * FIN / 8 + 255) / 256, 256>>>(x, xH, NN * FIN / 8);

    const int GRID_M = (NN + 127) / 128;

    // stats must be zero before layer-0 GEMM2; subsequent zeroing by k_bnprep
    k_zero<<<2, 256>>>(stats, 2 * FH);

    for (int l = 0; l < 1 + NLAYER_REST; l++) {
        int fin = (l == 0) ? FIN : FH;
        const float* b1    = (l == 0) ? b1_0 : b1s + (size_t)(l - 1) * FH;
        const float* b2    = (l == 0) ? b2_0 : b2s + (size_t)(l - 1) * FH;
        const __half* w1H = wH + (size_t)(l == 0 ? 0 : 2 * l) * SLOT;
        const __half* w2H = wH + (size_t)(l == 0 ? 1 : 2 * l + 1) * SLOT;

        if (l == 0) {
            int total = NN * (fin / 8);
            k_agg_split<<<(total + 255) / 256, 256>>>(xH, rowptr, col, aggH, fin, total);
        } else {
            const float* gamma = (l == 1) ? g_0  : gs  + (size_t)(l - 2) * FH;
            const float* beta  = (l == 1) ? be_0 : bes + (size_t)(l - 2) * FH;
            k_bnprep<<<1, FH>>>(stats, gamma, beta, bnscale, bnshift, NN);
            int total = NN * (FH / 8);
            k_agg_bn_split<<<(total + 255) / 256, 256>>>(preH, bnscale, bnshift,
                                                         rowptr, col, aggH, total);
        }
        // mid = relu(agg @ W1 + b1): 1-pass fp16
        k_gemm_mma<<<dim3(2, GRID_M), 256>>>(aggH, aggH, w1H, w1H, b1,
                                             nullptr, midH, nullptr, NN, fin, 2, 1);
        // pre-BN = mid @ W2 + b2 -> preH (fp16 hi) + exact fp32 stats: 1-pass
        k_gemm_mma<<<dim3(2, GRID_M), 256>>>(midH, midH, w2H, w2H, b2,
                                             nullptr, preH, stats, NN, FH, 3, 1);
    }

    // global mean pool with fused BN(last)+ReLU
    k_bnprep<<<1, FH>>>(stats, gs + (size_t)(NLAYER_REST - 1) * FH,
                        bes + (size_t)(NLAYER_REST - 1) * FH, bnscale, bnshift, NN);
    k_zero_pool<<<(GG * FH + 255) / 256, 256>>>(pool, cnt);
    k_pool_scatter_bn<<<(NN * (FH / 4) + 255) / 256, 256>>>(preH, bnscale, bnshift,
                                                            batch, pool, cnt);
    k_pool_div_split<<<(GG * FH / 4 + 255) / 256, 256>>>(pool, cnt, poolH, poolL);

    // predictor: post-pooling, full 3-pass precision
    k_gemm_mma<<<dim3(2, GG / 128), 256>>>(poolH, poolL, wH + 10 * SLOT, wL + 10 * SLOT, bp1,
                                           gmid, nullptr, nullptr, GG, FH, 1, 3);
    k_final<<<(GG * TT + 127) / 128, 128>>>(gmid, Wp2, bp2, out);
}